// round 2
// baseline (speedup 1.0000x reference)
#include <cuda_runtime.h>
#include <cuda_bf16.h>
#include <math.h>

#define SEQ   8192
#define EMB   256
#define HID   128      // per-direction hidden
#define GATES 512      // 4*HID
#define NTAG  14
#define START 12
#define STOP  13
#define NEG   (-10000.0f)

// ---------------- scratch (device globals; no allocation) ----------------
__device__ float d_pre[2][SEQ][GATES];      // 32 MB: input projection + biases
__device__ float d_h[2][SEQ][HID];          // 8 MB: hidden states (dir1 in reversed-step order)
__device__ float d_feats[SEQ * 16];         // padded stride 16

// ---------------- kernel 1: input projection GEMM -------------------------
// d_pre[dir][t][r] = sum_k emb[sent[t_eff]][k] * wih[r][k] + bih[r] + bhh[r]
// t_eff = t (dir 0) or SEQ-1-t (dir 1). Tile 64t x 64r, K chunks of 64.
__global__ void __launch_bounds__(256) prep_kernel(
    const int* __restrict__ sent, const float* __restrict__ emb,
    const float* __restrict__ wih_f, const float* __restrict__ bih_f, const float* __restrict__ bhh_f,
    const float* __restrict__ wih_b, const float* __restrict__ bih_b, const float* __restrict__ bhh_b)
{
    const int dir = blockIdx.z;
    const float* wih = dir ? wih_b : wih_f;
    const float* bih = dir ? bih_b : bih_f;
    const float* bhh = dir ? bhh_b : bhh_f;
    const int t0 = blockIdx.x * 64;
    const int r0 = blockIdx.y * 64;

    __shared__ float xs[64][65];   // [k][t], padded
    __shared__ float ws[64][65];   // [k][r], padded
    __shared__ int   sidx[64];

    const int tid = threadIdx.x;
    if (tid < 64) {
        int t = t0 + tid;
        sidx[tid] = sent[dir ? (SEQ - 1 - t) : t];
    }

    const int tx = tid & 15;       // t sub-index
    const int ty = tid >> 4;       // r sub-index
    float acc[4][4];
    #pragma unroll
    for (int i = 0; i < 4; i++)
        #pragma unroll
        for (int j = 0; j < 4; j++) acc[i][j] = 0.f;

    for (int kc = 0; kc < EMB; kc += 64) {
        __syncthreads();
        #pragma unroll
        for (int e = 0; e < 16; e++) {
            int lin = e * 256 + tid;          // 0..4095
            int kk  = lin & 63;
            int row = lin >> 6;
            xs[kk][row] = emb[(size_t)sidx[row] * EMB + kc + kk];
            ws[kk][row] = wih[(size_t)(r0 + row) * EMB + kc + kk];
        }
        __syncthreads();
        #pragma unroll 8
        for (int kk = 0; kk < 64; kk++) {
            float xv[4], wv[4];
            #pragma unroll
            for (int i = 0; i < 4; i++) xv[i] = xs[kk][tx + 16 * i];
            #pragma unroll
            for (int j = 0; j < 4; j++) wv[j] = ws[kk][ty + 16 * j];
            #pragma unroll
            for (int i = 0; i < 4; i++)
                #pragma unroll
                for (int j = 0; j < 4; j++) acc[i][j] += xv[i] * wv[j];
        }
    }

    #pragma unroll
    for (int i = 0; i < 4; i++) {
        int t = t0 + tx + 16 * i;
        #pragma unroll
        for (int j = 0; j < 4; j++) {
            int r = r0 + ty + 16 * j;
            d_pre[dir][t][r] = acc[i][j] + bih[r] + bhh[r];
        }
    }
}

// ---------------- kernel 2: sequential LSTM (one block per direction) -----
#define RW 80                         // weight columns held in registers
#define SW (HID - RW)                 // 48 columns from smem
#define LSTM_SMEM ((SW * GATES + HID + GATES) * 4)

__device__ __forceinline__ float sigmoidf_(float x) {
    return 1.0f / (1.0f + expf(-x));
}

__global__ void __launch_bounds__(GATES, 1) lstm_kernel(
    const float* __restrict__ whh_f, const float* __restrict__ whh_b)
{
    const int dir = blockIdx.x;
    const float* __restrict__ whh = dir ? whh_b : whh_f;
    const float* __restrict__ pre = &d_pre[dir][0][0];
    float* __restrict__ hout = &d_h[dir][0][0];

    extern __shared__ float sm[];
    float* Wt   = sm;                      // [SW][GATES] transposed tail weights
    float* hsm  = sm + SW * GATES;         // [HID]
    float* gbuf = hsm + HID;               // [GATES]

    const int r = threadIdx.x;

    // register-resident weight head: whh[r][0..RW)
    float wreg[RW];
    #pragma unroll
    for (int i = 0; i < RW / 4; i++) {
        float4 v = *(const float4*)&whh[(size_t)r * HID + i * 4];
        wreg[i*4+0] = v.x; wreg[i*4+1] = v.y; wreg[i*4+2] = v.z; wreg[i*4+3] = v.w;
    }
    // smem tail, transposed for conflict-free reads: Wt[k][r] = whh[r][RW+k]
    #pragma unroll
    for (int i = 0; i < SW; i++) Wt[i * GATES + r] = whh[(size_t)r * HID + RW + i];

    if (r < HID) hsm[r] = 0.f;
    float c = 0.f;
    __syncthreads();

    float pre_next = pre[r];   // t = 0
    for (int t = 0; t < SEQ; t++) {
        float acc = pre_next;
        if (t + 1 < SEQ) pre_next = pre[(size_t)(t + 1) * GATES + r];

        float a0 = 0.f, a1 = 0.f, a2 = 0.f, a3 = 0.f;
        #pragma unroll
        for (int k = 0; k < RW; k += 4) {
            float4 hv = *(const float4*)&hsm[k];
            a0 += wreg[k+0] * hv.x;
            a1 += wreg[k+1] * hv.y;
            a2 += wreg[k+2] * hv.z;
            a3 += wreg[k+3] * hv.w;
        }
        #pragma unroll
        for (int k = 0; k < SW; k += 4) {
            float4 hv = *(const float4*)&hsm[RW + k];
            a0 += Wt[(k+0) * GATES + r] * hv.x;
            a1 += Wt[(k+1) * GATES + r] * hv.y;
            a2 += Wt[(k+2) * GATES + r] * hv.z;
            a3 += Wt[(k+3) * GATES + r] * hv.w;
        }
        acc += (a0 + a1) + (a2 + a3);
        gbuf[r] = acc;
        __syncthreads();

        if (r < HID) {
            float ig = sigmoidf_(gbuf[r]);
            float fg = sigmoidf_(gbuf[HID + r]);
            float gg = tanhf(gbuf[2 * HID + r]);
            float og = sigmoidf_(gbuf[3 * HID + r]);
            c = fg * c + ig * gg;
            float h = og * tanhf(c);
            hsm[r] = h;
            hout[(size_t)t * HID + r] = h;
        }
        __syncthreads();
    }
}

// ---------------- kernel 3: tag feats ------------------------------------
// feats[t][n] = hf[t] . wtag[n][0:128] + hb_orig[t] . wtag[n][128:256] + btag[n]
// hb_orig[t] = d_h[1][SEQ-1-t]
__global__ void __launch_bounds__(256) feats_kernel(
    const float* __restrict__ wtag, const float* __restrict__ btag)
{
    const int tid = threadIdx.x;
    const int n  = tid & 15;
    const int tl = tid >> 4;
    const int t  = blockIdx.x * 16 + tl;
    if (n >= NTAG) return;

    const float* __restrict__ hf = &d_h[0][t][0];
    const float* __restrict__ hb = &d_h[1][SEQ - 1 - t][0];
    const float* __restrict__ w  = &wtag[n * 256];

    float acc = btag[n];
    #pragma unroll 8
    for (int j = 0; j < HID; j += 4) {
        float4 h4 = *(const float4*)&hf[j];
        float4 w4 = *(const float4*)&w[j];
        acc += h4.x * w4.x + h4.y * w4.y + h4.z * w4.z + h4.w * w4.w;
    }
    #pragma unroll 8
    for (int j = 0; j < HID; j += 4) {
        float4 h4 = *(const float4*)&hb[j];
        float4 w4 = *(const float4*)&w[HID + j];
        acc += h4.x * w4.x + h4.y * w4.y + h4.z * w4.z + h4.w * w4.w;
    }
    d_feats[t * 16 + n] = acc;
}

// ---------------- kernel 4: Viterbi (sequential, bit-faithful order) ------
#define VCHUNK 512
#define NCHUNK (SEQ / VCHUNK)
#define VIT_SMEM (SEQ * 16 /*bptr bytes*/ + 2 * VCHUNK * 16 * 4 /*feats dbuf*/ + 64 /*fv*/)

__global__ void __launch_bounds__(256, 1) viterbi_kernel(
    const float* __restrict__ trans, float* __restrict__ out)
{
    extern __shared__ unsigned char vsm[];
    unsigned char* bp = vsm;                                  // [SEQ][16]
    float* fbuf = (float*)(vsm + SEQ * 16);                   // [2][VCHUNK*16]
    float* fvs  = fbuf + 2 * VCHUNK * 16;                     // [16]

    const int tid  = threadIdx.x;
    const int warp = tid >> 5;

    // preload chunk 0
    for (int i = tid; i < VCHUNK * 16; i += 256) fbuf[i] = d_feats[i];
    if (tid < 16) fvs[tid] = (tid == START) ? 0.f : NEG;

    float tr[NTAG];
    if (tid < NTAG) {
        #pragma unroll
        for (int p = 0; p < NTAG; p++) tr[p] = trans[tid * NTAG + p];
    }
    __syncthreads();

    for (int ch = 0; ch < NCHUNK; ch++) {
        const int buf = ch & 1;
        if (warp > 0) {
            if (ch + 1 < NCHUNK) {
                const int nbuf = buf ^ 1;
                for (int i = tid - 32; i < VCHUNK * 16; i += 224)
                    fbuf[nbuf * VCHUNK * 16 + i] = d_feats[(ch + 1) * VCHUNK * 16 + i];
            }
        } else {
            const float* fb = fbuf + buf * VCHUNK * 16;
            for (int s = 0; s < VCHUNK; s++) {
                const int t = ch * VCHUNK + s;
                float best = 0.f; int barg = 0;
                if (tid < NTAG) {
                    best = fvs[0] + tr[0]; barg = 0;
                    #pragma unroll
                    for (int p = 1; p < NTAG; p++) {
                        float sc = fvs[p] + tr[p];
                        if (sc > best) { best = sc; barg = p; }   // strict > keeps first (jnp.argmax)
                    }
                    best += fb[s * 16 + tid];
                }
                __syncwarp();
                if (tid < NTAG) {
                    fvs[tid] = best;
                    bp[t * 16 + tid] = (unsigned char)barg;
                }
                __syncwarp();
            }
        }
        __syncthreads();
    }

    if (tid == 0) {
        float best = fvs[0] + trans[STOP * NTAG + 0]; int barg = 0;
        #pragma unroll
        for (int p = 1; p < NTAG; p++) {
            float sc = fvs[p] + trans[STOP * NTAG + p];
            if (sc > best) { best = sc; barg = p; }
        }
        out[0] = best;                       // score
        int tag = barg;
        for (int t = SEQ - 1; t >= 0; t--) { // path[t]=tag; tag=bptr[t][tag]
            out[1 + t] = (float)tag;
            tag = bp[t * 16 + tag];
        }
    }
}

// ---------------- launch ---------------------------------------------------
extern "C" void kernel_launch(void* const* d_in, const int* in_sizes, int n_in,
                              void* d_out, int out_size)
{
    const int*   sent  = (const int*)  d_in[0];
    const float* emb   = (const float*)d_in[1];
    const float* wih_f = (const float*)d_in[2];
    const float* whh_f = (const float*)d_in[3];
    const float* bih_f = (const float*)d_in[4];
    const float* bhh_f = (const float*)d_in[5];
    const float* wih_b = (const float*)d_in[6];
    const float* whh_b = (const float*)d_in[7];
    const float* bih_b = (const float*)d_in[8];
    const float* bhh_b = (const float*)d_in[9];
    const float* wtag  = (const float*)d_in[10];
    const float* btag  = (const float*)d_in[11];
    const float* trans = (const float*)d_in[12];
    float* out = (float*)d_out;

    cudaFuncSetAttribute(lstm_kernel,    cudaFuncAttributeMaxDynamicSharedMemorySize, LSTM_SMEM);
    cudaFuncSetAttribute(viterbi_kernel, cudaFuncAttributeMaxDynamicSharedMemorySize, VIT_SMEM);

    prep_kernel<<<dim3(SEQ / 64, GATES / 64, 2), 256>>>(
        sent, emb, wih_f, bih_f, bhh_f, wih_b, bih_b, bhh_b);
    lstm_kernel<<<2, GATES, LSTM_SMEM>>>(whh_f, whh_b);
    feats_kernel<<<SEQ / 16, 256>>>(wtag, btag);
    viterbi_kernel<<<1, 256, VIT_SMEM>>>(trans, out);
}

// round 3
// speedup vs baseline: 1.2883x; 1.2883x over previous
#include <cuda_runtime.h>
#include <cuda_bf16.h>
#include <math.h>

#define SEQ   8192
#define EMB   256
#define HID   128      // per-direction hidden
#define GATES 512      // 4*HID
#define NTAG  14
#define START 12
#define STOP  13
#define NEG   (-10000.0f)

// ---------------- scratch (device globals; no allocation) ----------------
__device__ float d_pre[2][SEQ][GATES];      // 32 MB: input projection + biases
__device__ float d_h[2][SEQ][HID];          // 8 MB: hidden states (dir1 in reversed-step order)
__device__ float d_feats[SEQ * 16];         // padded stride 16

// ---------------- small PTX helpers ---------------------------------------
__device__ __forceinline__ unsigned smem_u32(const void* p) {
    unsigned a;
    asm("{ .reg .u64 t; cvta.to.shared.u64 t, %1; cvt.u32.u64 %0, t; }"
        : "=r"(a) : "l"(p));
    return a;
}
__device__ __forceinline__ unsigned mapa_u32(unsigned a, unsigned rank) {
    unsigned r;
    asm("mapa.shared::cluster.u32 %0, %1, %2;" : "=r"(r) : "r"(a), "r"(rank));
    return r;
}
__device__ __forceinline__ void st_remote_f32(unsigned addr, float v) {
    asm volatile("st.shared::cluster.f32 [%0], %1;" :: "r"(addr), "f"(v) : "memory");
}
__device__ __forceinline__ void mbar_init(unsigned addr, unsigned cnt) {
    asm volatile("mbarrier.init.shared.b64 [%0], %1;" :: "r"(addr), "r"(cnt) : "memory");
}
__device__ __forceinline__ void mbar_arrive_remote(unsigned addr) {
    asm volatile("mbarrier.arrive.release.cluster.shared::cluster.b64 _, [%0];"
                 :: "r"(addr) : "memory");
}
__device__ __forceinline__ void mbar_wait_acq_cluster(unsigned addr, unsigned parity) {
    asm volatile(
        "{\n\t"
        ".reg .pred P;\n\t"
        "WL%=:\n\t"
        "mbarrier.try_wait.parity.acquire.cluster.shared::cta.b64 P, [%0], %1, 0x989680;\n\t"
        "@P bra WD%=;\n\t"
        "bra WL%=;\n\t"
        "WD%=:\n\t"
        "}"
        :: "r"(addr), "r"(parity) : "memory");
}
__device__ __forceinline__ void cluster_sync_() {
    asm volatile("barrier.cluster.arrive.aligned;" ::: "memory");
    asm volatile("barrier.cluster.wait.aligned;" ::: "memory");
}

__device__ __forceinline__ float sig_fast(float x) {
    return __fdividef(1.0f, 1.0f + __expf(-x));
}
__device__ __forceinline__ float tanh_fast(float x) {
    return __fdividef(2.0f, 1.0f + __expf(-2.0f * x)) - 1.0f;
}

// ---------------- kernel 1: input projection GEMM -------------------------
__global__ void __launch_bounds__(256) prep_kernel(
    const int* __restrict__ sent, const float* __restrict__ emb,
    const float* __restrict__ wih_f, const float* __restrict__ bih_f, const float* __restrict__ bhh_f,
    const float* __restrict__ wih_b, const float* __restrict__ bih_b, const float* __restrict__ bhh_b)
{
    const int dir = blockIdx.z;
    const float* wih = dir ? wih_b : wih_f;
    const float* bih = dir ? bih_b : bih_f;
    const float* bhh = dir ? bhh_b : bhh_f;
    const int t0 = blockIdx.x * 64;
    const int r0 = blockIdx.y * 64;

    __shared__ float xs[64][65];
    __shared__ float ws[64][65];
    __shared__ int   sidx[64];

    const int tid = threadIdx.x;
    if (tid < 64) {
        int t = t0 + tid;
        sidx[tid] = sent[dir ? (SEQ - 1 - t) : t];
    }

    const int tx = tid & 15;
    const int ty = tid >> 4;
    float acc[4][4];
    #pragma unroll
    for (int i = 0; i < 4; i++)
        #pragma unroll
        for (int j = 0; j < 4; j++) acc[i][j] = 0.f;

    for (int kc = 0; kc < EMB; kc += 64) {
        __syncthreads();
        #pragma unroll
        for (int e = 0; e < 16; e++) {
            int lin = e * 256 + tid;
            int kk  = lin & 63;
            int row = lin >> 6;
            xs[kk][row] = emb[(size_t)sidx[row] * EMB + kc + kk];
            ws[kk][row] = wih[(size_t)(r0 + row) * EMB + kc + kk];
        }
        __syncthreads();
        #pragma unroll 8
        for (int kk = 0; kk < 64; kk++) {
            float xv[4], wv[4];
            #pragma unroll
            for (int i = 0; i < 4; i++) xv[i] = xs[kk][tx + 16 * i];
            #pragma unroll
            for (int j = 0; j < 4; j++) wv[j] = ws[kk][ty + 16 * j];
            #pragma unroll
            for (int i = 0; i < 4; i++)
                #pragma unroll
                for (int j = 0; j < 4; j++) acc[i][j] += xv[i] * wv[j];
        }
    }

    #pragma unroll
    for (int i = 0; i < 4; i++) {
        int t = t0 + tx + 16 * i;
        #pragma unroll
        for (int j = 0; j < 4; j++) {
            int r = r0 + ty + 16 * j;
            d_pre[dir][t][r] = acc[i][j] + bih[r] + bhh[r];
        }
    }
}

// ---------------- kernel 2: clustered sequential LSTM ---------------------
// 4 CTAs, clusters of 2. blockIdx.x: {0,1}=dir0 cluster, {2,3}=dir1 cluster.
// Each CTA: 256 threads, one full gate row per thread (128 weights in regs),
// owns 64 hidden units; h halves exchanged with peer CTA via DSMEM per step.
__global__ void __launch_bounds__(256, 1) __cluster_dims__(2, 1, 1)
lstm_kernel(const float* __restrict__ whh_f, const float* __restrict__ whh_b)
{
    const int dir  = blockIdx.x >> 1;
    const int rank = blockIdx.x & 1;
    const float* __restrict__ whh = dir ? whh_b : whh_f;
    const float* __restrict__ pre  = &d_pre[dir][0][0];
    float* __restrict__ hout = &d_h[dir][0][0];

    __shared__ float hsm[2][HID];             // double-buffered full h
    __shared__ float acts[256];
    __shared__ unsigned long long mbar[2];

    const int tid = threadIdx.x;
    const int g   = tid >> 6;                 // gate 0..3 (i,f,g,o)
    const int j   = tid & 63;                 // local unit index
    const int u   = rank * 64 + j;            // global hidden unit
    const int row = g * 128 + u;              // global gate row

    float wA[64], wB[64];                     // my-half / other-half columns
    {
        const float* wr = &whh[(size_t)row * HID];
        const int la = rank * 64, lb = (rank ^ 1) * 64;
        #pragma unroll
        for (int k = 0; k < 64; k += 4) {
            float4 va = *(const float4*)&wr[la + k];
            wA[k] = va.x; wA[k+1] = va.y; wA[k+2] = va.z; wA[k+3] = va.w;
            float4 vb = *(const float4*)&wr[lb + k];
            wB[k] = vb.x; wB[k+1] = vb.y; wB[k+2] = vb.z; wB[k+3] = vb.w;
        }
    }

    const unsigned h_loc  = smem_u32(&hsm[0][0]);
    const unsigned mb_loc = smem_u32(&mbar[0]);
    const unsigned peer   = rank ^ 1;
    const unsigned h_rm   = mapa_u32(h_loc, peer);
    const unsigned mb_rm  = mapa_u32(mb_loc, peer);

    if (tid < 2) mbar_init(mb_loc + tid * 8, 64);
    __syncthreads();
    cluster_sync_();                          // mbarriers visible cluster-wide

    float c = 0.f;
    float pre_cur = pre[row];

    // ---- t = 0 peel: h=0, gates = pre ----
    {
        acts[tid] = (g == 2) ? tanh_fast(pre_cur) : sig_fast(pre_cur);
        pre_cur = pre[GATES + row];           // prefetch t=1
        __syncthreads();
        if (tid < 64) {
            float iv = acts[tid], fv = acts[64 + tid], gv = acts[128 + tid], ov = acts[192 + tid];
            c = fv * c + iv * gv;
            float h = ov * tanh_fast(c);
            hsm[1][u] = h;                    // buffer for t=1
            hout[u] = h;                      // hout[0][u]
            st_remote_f32(h_rm + (unsigned)(HID + u) * 4u, h);
            mbar_arrive_remote(mb_rm + 8);    // mbar[1]
        }
        __syncthreads();
    }

    // ---- main loop t = 1 .. SEQ-1 ----
    for (int t = 1; t < SEQ; t++) {
        float pre_nxt = 0.f;
        if (t + 1 < SEQ) pre_nxt = pre[(size_t)(t + 1) * GATES + row];

        const int b = t & 1;
        float a0 = 0.f, a1 = 0.f, a2 = 0.f, a3 = 0.f;

        // local half (written by this CTA last step)
        {
            const float* hb = &hsm[b][rank * 64];
            #pragma unroll
            for (int k = 0; k < 64; k += 4) {
                float4 hv = *(const float4*)&hb[k];
                a0 += wA[k+0] * hv.x;
                a1 += wA[k+1] * hv.y;
                a2 += wA[k+2] * hv.z;
                a3 += wA[k+3] * hv.w;
            }
        }
        // wait for peer's half of h(t); parity = ((t-1)>>1)&1 for both buffers
        mbar_wait_acq_cluster(mb_loc + b * 8, ((t - 1) >> 1) & 1);
        {
            const float* hb = &hsm[b][(rank ^ 1) * 64];
            #pragma unroll
            for (int k = 0; k < 64; k += 4) {
                float4 hv = *(const float4*)&hb[k];
                a0 += wB[k+0] * hv.x;
                a1 += wB[k+1] * hv.y;
                a2 += wB[k+2] * hv.z;
                a3 += wB[k+3] * hv.w;
            }
        }
        float acc = pre_cur + ((a0 + a1) + (a2 + a3));

        acts[tid] = (g == 2) ? tanh_fast(acc) : sig_fast(acc);
        __syncthreads();

        if (tid < 64) {
            float iv = acts[tid], fv = acts[64 + tid], gv = acts[128 + tid], ov = acts[192 + tid];
            c = fv * c + iv * gv;
            float h = ov * tanh_fast(c);
            const int nb = (t + 1) & 1;
            hsm[nb][u] = h;
            hout[(size_t)t * HID + u] = h;
            if (t < SEQ - 1) {
                st_remote_f32(h_rm + (unsigned)(nb * HID + u) * 4u, h);
                mbar_arrive_remote(mb_rm + nb * 8);
            }
        }
        __syncthreads();
        pre_cur = pre_nxt;
    }

    cluster_sync_();
}

// ---------------- kernel 3: tag feats ------------------------------------
__global__ void __launch_bounds__(256) feats_kernel(
    const float* __restrict__ wtag, const float* __restrict__ btag)
{
    const int tid = threadIdx.x;
    const int n  = tid & 15;
    const int tl = tid >> 4;
    const int t  = blockIdx.x * 16 + tl;
    if (n >= NTAG) return;

    const float* __restrict__ hf = &d_h[0][t][0];
    const float* __restrict__ hb = &d_h[1][SEQ - 1 - t][0];
    const float* __restrict__ w  = &wtag[n * 256];

    float acc = btag[n];
    #pragma unroll 8
    for (int jj = 0; jj < HID; jj += 4) {
        float4 h4 = *(const float4*)&hf[jj];
        float4 w4 = *(const float4*)&w[jj];
        acc += h4.x * w4.x + h4.y * w4.y + h4.z * w4.z + h4.w * w4.w;
    }
    #pragma unroll 8
    for (int jj = 0; jj < HID; jj += 4) {
        float4 h4 = *(const float4*)&hb[jj];
        float4 w4 = *(const float4*)&w[HID + jj];
        acc += h4.x * w4.x + h4.y * w4.y + h4.z * w4.z + h4.w * w4.w;
    }
    d_feats[t * 16 + n] = acc;
}

// ---------------- kernel 4: Viterbi (sequential, tree argmax) -------------
#define VCHUNK 512
#define NCHUNK (SEQ / VCHUNK)
#define VIT_SMEM (SEQ * 16 + 2 * VCHUNK * 16 * 4 + 64)

// ordered combine: pick right only if STRICTLY greater (first-max semantics)
#define CMB(va, ia, vb, ib) { bool _gt = ((vb) > (va)); (va) = _gt ? (vb) : (va); (ia) = _gt ? (ib) : (ia); }

__global__ void __launch_bounds__(256, 1) viterbi_kernel(
    const float* __restrict__ trans, float* __restrict__ out)
{
    extern __shared__ unsigned char vsm[];
    unsigned char* bp = vsm;                                  // [SEQ][16]
    float* fbuf = (float*)(vsm + SEQ * 16);                   // [2][VCHUNK*16]
    float* fvs  = fbuf + 2 * VCHUNK * 16;                     // [16]

    const int tid  = threadIdx.x;
    const int warp = tid >> 5;

    for (int i = tid; i < VCHUNK * 16; i += 256) fbuf[i] = d_feats[i];
    if (tid < 16) fvs[tid] = (tid == START) ? 0.f : NEG;

    float tr[NTAG];
    if (tid < NTAG) {
        #pragma unroll
        for (int p = 0; p < NTAG; p++) tr[p] = trans[tid * NTAG + p];
    }
    __syncthreads();

    for (int ch = 0; ch < NCHUNK; ch++) {
        const int buf = ch & 1;
        if (warp > 0) {
            if (ch + 1 < NCHUNK) {
                const int nbuf = buf ^ 1;
                for (int i = tid - 32; i < VCHUNK * 16; i += 224)
                    fbuf[nbuf * VCHUNK * 16 + i] = d_feats[(ch + 1) * VCHUNK * 16 + i];
            }
        } else {
            const float* fb = fbuf + buf * VCHUNK * 16;
            for (int s = 0; s < VCHUNK; s++) {
                const int t = ch * VCHUNK + s;
                float best = 0.f; int barg = 0;
                if (tid < NTAG) {
                    float sv[14];
                    #pragma unroll
                    for (int p = 0; p < NTAG; p++) sv[p] = fvs[p] + tr[p];
                    float v[7]; int ix[7];
                    #pragma unroll
                    for (int k = 0; k < 7; k++) {
                        bool gt = sv[2*k+1] > sv[2*k];
                        v[k]  = gt ? sv[2*k+1] : sv[2*k];
                        ix[k] = gt ? (2*k+1) : (2*k);
                    }
                    CMB(v[0], ix[0], v[1], ix[1]);
                    CMB(v[2], ix[2], v[3], ix[3]);
                    CMB(v[4], ix[4], v[5], ix[5]);
                    CMB(v[0], ix[0], v[2], ix[2]);
                    CMB(v[4], ix[4], v[6], ix[6]);
                    CMB(v[0], ix[0], v[4], ix[4]);
                    best = v[0] + fb[s * 16 + tid];
                    barg = ix[0];
                }
                __syncwarp();
                if (tid < NTAG) {
                    fvs[tid] = best;
                    bp[t * 16 + tid] = (unsigned char)barg;
                }
                __syncwarp();
            }
        }
        __syncthreads();
    }

    if (tid == 0) {
        float best = fvs[0] + trans[STOP * NTAG + 0]; int barg = 0;
        #pragma unroll
        for (int p = 1; p < NTAG; p++) {
            float sc = fvs[p] + trans[STOP * NTAG + p];
            if (sc > best) { best = sc; barg = p; }
        }
        out[0] = best;
        int tag = barg;
        for (int t = SEQ - 1; t >= 0; t--) {
            out[1 + t] = (float)tag;
            tag = bp[t * 16 + tag];
        }
    }
}

// ---------------- launch ---------------------------------------------------
extern "C" void kernel_launch(void* const* d_in, const int* in_sizes, int n_in,
                              void* d_out, int out_size)
{
    const int*   sent  = (const int*)  d_in[0];
    const float* emb   = (const float*)d_in[1];
    const float* wih_f = (const float*)d_in[2];
    const float* whh_f = (const float*)d_in[3];
    const float* bih_f = (const float*)d_in[4];
    const float* bhh_f = (const float*)d_in[5];
    const float* wih_b = (const float*)d_in[6];
    const float* whh_b = (const float*)d_in[7];
    const float* bih_b = (const float*)d_in[8];
    const float* bhh_b = (const float*)d_in[9];
    const float* wtag  = (const float*)d_in[10];
    const float* btag  = (const float*)d_in[11];
    const float* trans = (const float*)d_in[12];
    float* out = (float*)d_out;

    cudaFuncSetAttribute(viterbi_kernel, cudaFuncAttributeMaxDynamicSharedMemorySize, VIT_SMEM);

    prep_kernel<<<dim3(SEQ / 64, GATES / 64, 2), 256>>>(
        sent, emb, wih_f, bih_f, bhh_f, wih_b, bih_b, bhh_b);
    lstm_kernel<<<4, 256>>>(whh_f, whh_b);
    feats_kernel<<<SEQ / 16, 256>>>(wtag, btag);
    viterbi_kernel<<<1, 256, VIT_SMEM>>>(trans, out);
}